// round 11
// baseline (speedup 1.0000x reference)
#include <cuda_runtime.h>
#include <cuda_fp16.h>
#include <math.h>
#include <stdint.h>

#define N_ROWS_MAX 100000
#define NUM_SCENES_MAX 5001
#define D 64
#define NGH 16
#define NSC 10
#define EPSF 1e-10f
#define FULL 0xFFFFFFFFu

#define WPB 8           // warps per block
#define RPW 16          // rows per warp
#define RPB 128         // rows per block

#define ASTRIDE 136     // A-tile row stride in halfs (272B) — conflict-free

typedef unsigned long long ull;

// ---- scratch (device globals per allocation rules) ----
__device__ __half2 g_rs_h[(size_t)N_ROWS_MAX * 32];     // rs/(||rs||^2+eps) fp16
__device__ float2  g_ss[N_ROWS_MAX];                    // (scale = sq+eps, selfsim)
__device__ uint2   g_Bfrag[64 * 32];                    // [kstep*8+ntile][lane]
__device__ uint2   g_sc_h[(size_t)NUM_SCENES_MAX * 16]; // scene_emb fp16 shadow

// ---- packed f32x2 helpers ----
__device__ __forceinline__ ull pk2(float x, float y) {
    ull r; asm("mov.b64 %0, {%1, %2};" : "=l"(r) : "f"(x), "f"(y)); return r;
}
__device__ __forceinline__ float2 upk2(ull v) {
    float2 r; asm("mov.b64 {%0, %1}, %2;" : "=f"(r.x), "=f"(r.y) : "l"(v)); return r;
}
__device__ __forceinline__ void fma2(ull& d, ull a, ull b, ull c) {
    asm("fma.rn.f32x2 %0, %1, %2, %3;" : "=l"(d) : "l"(a), "l"(b), "l"(c));
}

// ---------------------------------------------------------------------------
// Kernel A0: scene_emb -> fp16 shadow; agg_W -> HMMA B fragments.
// ---------------------------------------------------------------------------
__global__ void prep_kernel(const float* __restrict__ scene_emb,
                            const float* __restrict__ agg_W,
                            int n_scenes) {
    int gtid = blockIdx.x * blockDim.x + threadIdx.x;

    // B-fragment build: first 2048 threads, one uint2 each.
    if (gtid < 64 * 32) {
        int lane  = gtid & 31;
        int tile  = gtid >> 5;
        int kstep = tile >> 3;
        int ntile = tile & 7;
        int tid4  = lane & 3;
        int gid   = lane >> 2;
        int k0 = kstep * 16 + tid4 * 2;
        int n  = ntile * 8 + gid;
        __half2 r0 = __floats2half2_rn(agg_W[n * 128 + k0],     agg_W[n * 128 + k0 + 1]);
        __half2 r1 = __floats2half2_rn(agg_W[n * 128 + k0 + 8], agg_W[n * 128 + k0 + 9]);
        uint2 u;
        u.x = *reinterpret_cast<unsigned int*>(&r0);
        u.y = *reinterpret_cast<unsigned int*>(&r1);
        g_Bfrag[tile * 32 + lane] = u;
    }

    // scene fp16 shadow: one float4 -> uint2 per thread (grid covers all)
    int total = n_scenes * 16;
    if (gtid < total) {
        float4 v = ((const float4*)scene_emb)[gtid];
        __half2 h0 = __floats2half2_rn(v.x, v.y);
        __half2 h1 = __floats2half2_rn(v.z, v.w);
        uint2 u;
        u.x = *reinterpret_cast<unsigned int*>(&h0);
        u.y = *reinterpret_cast<unsigned int*>(&h1);
        g_sc_h[gtid] = u;
    }
}

// ---------------------------------------------------------------------------
// Kernel A: per-row scene sums (fp16 gathers) -> fp16 normalized table +
// (scale, selfsim). 16 threads/row, uint2 (4 halfs) per lane.
// ---------------------------------------------------------------------------
__global__ void rowsum_kernel(const int* __restrict__ cate_scene_pad,
                              int n_rows) {
    int gtid = blockIdx.x * blockDim.x + threadIdx.x;
    int row = gtid >> 4;
    int sub = gtid & 15;
    if (row >= n_rows) return;
    int lane = threadIdx.x & 31;
    int group_base = lane & 16;

    int myidx = 0;
    if (sub < NSC) myidx = __ldg(cate_scene_pad + (size_t)row * NSC + sub);

    float4 acc = make_float4(0.f, 0.f, 0.f, 0.f);
#pragma unroll
    for (int k = 0; k < NSC; k++) {
        int j = __shfl_sync(FULL, myidx, group_base + k);
        uint2 u = __ldg(g_sc_h + (size_t)j * 16 + sub);
        float2 f0 = __half22float2(*reinterpret_cast<__half2*>(&u.x));
        float2 f1 = __half22float2(*reinterpret_cast<__half2*>(&u.y));
        acc.x += f0.x; acc.y += f0.y; acc.z += f1.x; acc.w += f1.y;
    }

    float sq = acc.x * acc.x + acc.y * acc.y + acc.z * acc.z + acc.w * acc.w;
#pragma unroll
    for (int o = 8; o >= 1; o >>= 1)
        sq += __shfl_xor_sync(FULL, sq, o);

    float scale = sq + EPSF;
    float inv = 1.0f / scale;

    __half2 h0 = __floats2half2_rn(acc.x * inv, acc.y * inv);
    __half2 h1 = __floats2half2_rn(acc.z * inv, acc.w * inv);
    uint2 u;
    u.x = *reinterpret_cast<unsigned int*>(&h0);
    u.y = *reinterpret_cast<unsigned int*>(&h1);
    ((uint2*)g_rs_h)[(size_t)row * 16 + sub] = u;

    if (sub == 0) g_ss[row] = make_float2(scale, sq * inv * inv);
}

// Butterfly merge at xor-offset o.
__device__ __forceinline__ float bmerge(float a, float b, int o, int lane) {
    float x = (lane & o) ? b : a;
    float y = (lane & o) ? a : b;
    y = __shfl_xor_sync(FULL, y, o);
    return x + y;
}

__device__ __forceinline__ void mma16816(float* c, uint32_t a0, uint32_t a1,
                                         uint32_t a2, uint32_t a3,
                                         uint32_t b0, uint32_t b1) {
    asm volatile(
        "mma.sync.aligned.m16n8k16.row.col.f32.f16.f16.f32 "
        "{%0,%1,%2,%3}, {%4,%5,%6,%7}, {%8,%9}, {%0,%1,%2,%3};"
        : "+f"(c[0]), "+f"(c[1]), "+f"(c[2]), "+f"(c[3])
        : "r"(a0), "r"(a1), "r"(a2), "r"(a3), "r"(b0), "r"(b1));
}

// ---------------------------------------------------------------------------
// Kernel B: each warp owns 16 rows end-to-end.
//   Phase 1: half-warp row-pair attention -> h (fp16) into padded A tile.
//   Phase 2: HMMA in two 4-n-tile halves (register cap for 5 blocks/SM).
// ---------------------------------------------------------------------------
__global__ void __launch_bounds__(256, 5)
main_kernel(const float* __restrict__ cate_emb,
            const int* __restrict__ c_cate_pad,
            const float* __restrict__ agg_b,
            float* __restrict__ out,
            int n_rows, int v_cates) {
    __shared__ __half sA[RPB * ASTRIDE];   // 128 rows x 136 halfs (pad 8)

    int tid  = threadIdx.x;
    int warp = tid >> 5;
    int lane = tid & 31;

    int rowbase = blockIdx.x * RPB + warp * RPW;
    int half = lane >> 4;
    int sub  = lane & 15;
    int base = lane & 16;

    // ---- Phase 1: attention, 2 rows per iteration ----
#pragma unroll 1
    for (int rp = 0; rp < RPW / 2; rp++) {
        int row  = rowbase + 2 * rp + half;
        int vrow = row < n_rows ? row : n_rows - 1;

        int nidx = __ldg(c_cate_pad + (size_t)vrow * NGH + sub);

        uint2 us = __ldg((const uint2*)g_rs_h + (size_t)vrow * 16 + sub);
        float2 sf0 = __half22float2(*reinterpret_cast<__half2*>(&us.x));
        float2 sf1 = __half22float2(*reinterpret_cast<__half2*>(&us.y));
        float2 ss = g_ss[vrow];                 // (scale, selfsim)

        float dtp[16];
#pragma unroll
        for (int j = 0; j < 16; j++) {
            int p = __shfl_sync(FULL, nidx, base + j);
            uint2 u = __ldg((const uint2*)g_rs_h + (size_t)p * 16 + sub);
            float2 f0 = __half22float2(*reinterpret_cast<__half2*>(&u.x));
            float2 f1 = __half22float2(*reinterpret_cast<__half2*>(&u.y));
            dtp[j] = fmaf(f0.x, sf0.x, fmaf(f0.y, sf0.y,
                      fmaf(f1.x, sf1.x, f1.y * sf1.y)));
        }

#pragma unroll
        for (int i = 0; i < 8; i++) dtp[i] = bmerge(dtp[i], dtp[i + 8], 8, lane);
#pragma unroll
        for (int i = 0; i < 4; i++) dtp[i] = bmerge(dtp[i], dtp[i + 4], 4, lane);
#pragma unroll
        for (int i = 0; i < 2; i++) dtp[i] = bmerge(dtp[i], dtp[i + 2], 2, lane);
        dtp[0] = bmerge(dtp[0], dtp[1], 1, lane);

        float miu = (nidx < v_cates - 1) ? __expf(dtp[0]) : 0.f;

        float dv = miu;
#pragma unroll
        for (int o = 8; o >= 1; o >>= 1)
            dv += __shfl_xor_sync(FULL, dv, o);

        float miu_self = (vrow < v_cates - 1) ? __expf(ss.y) : 0.f;
        float rden = 1.0f / (dv + miu_self + EPSF);

        // aggregation: self + 16 neighbors, packed FFMA2, float4 lanes
        ulonglong2 cs = __ldg((const ulonglong2*)(cate_emb + (size_t)vrow * D) + sub);
        ull msd = pk2(miu_self, miu_self);
        ull acc01, acc23;
        fma2(acc01, msd, cs.x, pk2(0.f, 0.f));
        fma2(acc23, msd, cs.y, pk2(0.f, 0.f));
#pragma unroll
        for (int j = 0; j < 16; j++) {
            float m = __shfl_sync(FULL, miu, base + j);
            int   p = __shfl_sync(FULL, nidx, base + j);
            ulonglong2 cv = __ldg((const ulonglong2*)(cate_emb + (size_t)p * D) + sub);
            ull mm = pk2(m, m);
            fma2(acc01, mm, cv.x, acc01);
            fma2(acc23, mm, cv.y, acc23);
        }
        float2 g01 = upk2(acc01);
        float2 g23 = upk2(acc23);

        // h store (fp16): rs part at e=4sub..4sub+3, agg at e=64+4sub..
        int rt = warp * RPW + 2 * rp + half;
        __half* hrow = sA + rt * ASTRIDE;
        float sc = ss.x;
        __half2 p0 = __floats2half2_rn(sf0.x * sc, sf0.y * sc);
        __half2 p1 = __floats2half2_rn(sf1.x * sc, sf1.y * sc);
        uint2 w0;
        w0.x = *reinterpret_cast<unsigned int*>(&p0);
        w0.y = *reinterpret_cast<unsigned int*>(&p1);
        *(uint2*)(hrow + 4 * sub) = w0;

        __half2 q0 = __floats2half2_rn(g01.x * rden, g01.y * rden);
        __half2 q1 = __floats2half2_rn(g23.x * rden, g23.y * rden);
        uint2 w1;
        w1.x = *reinterpret_cast<unsigned int*>(&q0);
        w1.y = *reinterpret_cast<unsigned int*>(&q1);
        *(uint2*)(hrow + 64 + 4 * sub) = w1;
    }
    __syncwarp();

    // ---- Phase 2: HMMA matvec in two halves of 4 n-tiles (reg cap) ----
    int gid  = lane >> 2;      // 0..7
    int tid4 = lane & 3;       // 0..3

    const __half* a_base0 = sA + (warp * RPW + gid) * ASTRIDE + tid4 * 2;
    const __half* a_base1 = a_base0 + 8 * ASTRIDE;

    int grow0 = rowbase + gid;
    int grow1 = grow0 + 8;

#pragma unroll
    for (int hh = 0; hh < 2; hh++) {
        float acc[4][4];
#pragma unroll
        for (int n = 0; n < 4; n++)
#pragma unroll
            for (int i = 0; i < 4; i++) acc[n][i] = 0.f;

#pragma unroll
        for (int k = 0; k < 8; k++) {
            uint32_t a0 = *(const uint32_t*)(a_base0 + k * 16);
            uint32_t a1 = *(const uint32_t*)(a_base1 + k * 16);
            uint32_t a2 = *(const uint32_t*)(a_base0 + k * 16 + 8);
            uint32_t a3 = *(const uint32_t*)(a_base1 + k * 16 + 8);
#pragma unroll
            for (int n = 0; n < 4; n++) {
                uint2 bf = __ldg(&g_Bfrag[(k * 8 + hh * 4 + n) * 32 + lane]);
                mma16816(acc[n], a0, a1, a2, a3, bf.x, bf.y);
            }
        }

#pragma unroll
        for (int n = 0; n < 4; n++) {
            int col = (hh * 4 + n) * 8 + tid4 * 2;
            float2 bb = *(const float2*)(agg_b + col);
            if (grow0 < n_rows) {
                float v0 = acc[n][0] + bb.x;
                float v1 = acc[n][1] + bb.y;
                v0 = v0 > 0.f ? v0 : expm1f(v0);
                v1 = v1 > 0.f ? v1 : expm1f(v1);
                *(float2*)(out + (size_t)grow0 * D + col) = make_float2(v0, v1);
            }
            if (grow1 < n_rows) {
                float v2 = acc[n][2] + bb.x;
                float v3 = acc[n][3] + bb.y;
                v2 = v2 > 0.f ? v2 : expm1f(v2);
                v3 = v3 > 0.f ? v3 : expm1f(v3);
                *(float2*)(out + (size_t)grow1 * D + col) = make_float2(v2, v3);
            }
        }
    }
}

// ---------------------------------------------------------------------------
// Inputs (metadata order):
//  0 cids, 1 cate_emb_w [Vc,64], 2 scene_emb_w [Vs,64], 3 cate_scene_pad [N,10],
//  4 c_cate_pad [N,16], 5 agg_W [64,128], 6 agg_b [64]   -> out f32 [N,64]
// ---------------------------------------------------------------------------
extern "C" void kernel_launch(void* const* d_in, const int* in_sizes, int n_in,
                              void* d_out, int out_size) {
    const float* cate_emb       = (const float*)d_in[1];
    const float* scene_emb      = (const float*)d_in[2];
    const int*   cate_scene_pad = (const int*)d_in[3];
    const int*   c_cate_pad     = (const int*)d_in[4];
    const float* agg_W          = (const float*)d_in[5];
    const float* agg_b          = (const float*)d_in[6];
    float* out = (float*)d_out;

    int n_rows   = in_sizes[4] / NGH;   // 100000
    int v_cates  = in_sizes[1] / D;     // 100000
    int n_scenes = in_sizes[2] / D;     // 5001

    int prep_work = n_scenes * 16;      // >= 2048 always
    prep_kernel<<<(prep_work + 255) / 256, 256>>>(scene_emb, agg_W, n_scenes);

    int threadsA = 256;
    int blocksA = (n_rows * 16 + threadsA - 1) / threadsA;
    rowsum_kernel<<<blocksA, threadsA>>>(cate_scene_pad, n_rows);

    int blocksB = (n_rows + RPB - 1) / RPB;
    main_kernel<<<blocksB, 256>>>(cate_emb, c_cate_pad, agg_b,
                                  out, n_rows, v_cates);
}

// round 12
// speedup vs baseline: 1.0599x; 1.0599x over previous
#include <cuda_runtime.h>
#include <cuda_fp16.h>
#include <math.h>
#include <stdint.h>

#define N_ROWS_MAX 100000
#define D 64
#define NGH 16
#define NSC 10
#define EPSF 1e-10f
#define FULL 0xFFFFFFFFu

#define WPB 8           // warps per block
#define RPW 16          // rows per warp
#define RPB 128         // rows per block

#define ASTRIDE 136     // A-tile row stride in halfs (272B) — conflict-free

typedef unsigned long long ull;

// ---- scratch (device globals per allocation rules) ----
__device__ __half2 g_rs_h[(size_t)N_ROWS_MAX * 32];  // rs/(||rs||^2+eps) fp16
__device__ float2  g_ss[N_ROWS_MAX];                 // (scale = sq+eps, selfsim)
__device__ uint2   g_Bfrag[64 * 32];                 // [kstep*8+ntile][lane]

// ---- packed f32x2 helpers ----
__device__ __forceinline__ ull pk2(float x, float y) {
    ull r; asm("mov.b64 %0, {%1, %2};" : "=l"(r) : "f"(x), "f"(y)); return r;
}
__device__ __forceinline__ float2 upk2(ull v) {
    float2 r; asm("mov.b64 {%0, %1}, %2;" : "=f"(r.x), "=f"(r.y) : "l"(v)); return r;
}
__device__ __forceinline__ void fma2(ull& d, ull a, ull b, ull c) {
    asm("fma.rn.f32x2 %0, %1, %2, %3;" : "=l"(d) : "l"(a), "l"(b), "l"(c));
}

// ---------------------------------------------------------------------------
// Kernel A: per-row scene sums -> fp16 normalized table + (scale, selfsim);
// also builds per-lane HMMA B fragments of agg_W.
// ---------------------------------------------------------------------------
__global__ void rowsum_kernel(const float* __restrict__ scene_emb,
                              const int* __restrict__ cate_scene_pad,
                              const float* __restrict__ agg_W,
                              int n_rows) {
    int gtid = blockIdx.x * blockDim.x + threadIdx.x;

    // B-fragment build: first 2048 threads, one uint2 each.
    if (gtid < 64 * 32) {
        int lane  = gtid & 31;
        int tile  = gtid >> 5;
        int kstep = tile >> 3;
        int ntile = tile & 7;
        int tid4  = lane & 3;
        int gid   = lane >> 2;
        int k0 = kstep * 16 + tid4 * 2;
        int n  = ntile * 8 + gid;
        __half2 r0 = __floats2half2_rn(agg_W[n * 128 + k0],     agg_W[n * 128 + k0 + 1]);
        __half2 r1 = __floats2half2_rn(agg_W[n * 128 + k0 + 8], agg_W[n * 128 + k0 + 9]);
        uint2 u;
        u.x = *reinterpret_cast<unsigned int*>(&r0);
        u.y = *reinterpret_cast<unsigned int*>(&r1);
        g_Bfrag[tile * 32 + lane] = u;
    }

    int row = gtid >> 4;
    int sub = gtid & 15;
    if (row >= n_rows) return;
    int lane = threadIdx.x & 31;
    int group_base = lane & 16;

    int myidx = 0;
    if (sub < NSC) myidx = __ldg(cate_scene_pad + (size_t)row * NSC + sub);

    float4 acc = make_float4(0.f, 0.f, 0.f, 0.f);
#pragma unroll
    for (int k = 0; k < NSC; k++) {
        int j = __shfl_sync(FULL, myidx, group_base + k);
        float4 v = ((const float4*)(scene_emb + (size_t)j * D))[sub];
        acc.x += v.x; acc.y += v.y; acc.z += v.z; acc.w += v.w;
    }

    float sq = acc.x * acc.x + acc.y * acc.y + acc.z * acc.z + acc.w * acc.w;
#pragma unroll
    for (int o = 8; o >= 1; o >>= 1)
        sq += __shfl_xor_sync(FULL, sq, o);

    float scale = sq + EPSF;
    float inv = 1.0f / scale;

    __half2 h0 = __floats2half2_rn(acc.x * inv, acc.y * inv);
    __half2 h1 = __floats2half2_rn(acc.z * inv, acc.w * inv);
    uint2 u;
    u.x = *reinterpret_cast<unsigned int*>(&h0);
    u.y = *reinterpret_cast<unsigned int*>(&h1);
    ((uint2*)g_rs_h)[(size_t)row * 16 + sub] = u;

    if (sub == 0) g_ss[row] = make_float2(scale, sq * inv * inv);
}

// Butterfly merge at xor-offset o.
__device__ __forceinline__ float bmerge(float a, float b, int o, int lane) {
    float x = (lane & o) ? b : a;
    float y = (lane & o) ? a : b;
    y = __shfl_xor_sync(FULL, y, o);
    return x + y;
}

__device__ __forceinline__ void mma16816(float* c, uint32_t a0, uint32_t a1,
                                         uint32_t a2, uint32_t a3,
                                         uint32_t b0, uint32_t b1) {
    asm volatile(
        "mma.sync.aligned.m16n8k16.row.col.f32.f16.f16.f32 "
        "{%0,%1,%2,%3}, {%4,%5,%6,%7}, {%8,%9}, {%0,%1,%2,%3};"
        : "+f"(c[0]), "+f"(c[1]), "+f"(c[2]), "+f"(c[3])
        : "r"(a0), "r"(a1), "r"(a2), "r"(a3), "r"(b0), "r"(b1));
}

// ---------------------------------------------------------------------------
// Kernel B: each warp owns 16 rows end-to-end.
//   Phase 1: half-warp row-pair attention; all 8 iterations' neighbor-index
//            loads batched upfront (MLP=8) to hide the nidx->gather hop.
//   Phase 2: 64x HMMA m16n8k16 -> out[16][64] per warp; bias+ELU; direct STG.
// ---------------------------------------------------------------------------
__global__ void __launch_bounds__(256, 4)
main_kernel(const float* __restrict__ cate_emb,
            const int* __restrict__ c_cate_pad,
            const float* __restrict__ agg_b,
            float* __restrict__ out,
            int n_rows, int v_cates) {
    __shared__ __half sA[RPB * ASTRIDE];   // 128 rows x 136 halfs (pad 8)

    int tid  = threadIdx.x;
    int warp = tid >> 5;
    int lane = tid & 31;

    int rowbase = blockIdx.x * RPB + warp * RPW;
    int half = lane >> 4;
    int sub  = lane & 15;
    int base = lane & 16;

    // ---- batched neighbor-index prefetch for all 8 row-pair iterations ----
    int nid[RPW / 2];
#pragma unroll
    for (int rp = 0; rp < RPW / 2; rp++) {
        int row  = rowbase + 2 * rp + half;
        int vrow = row < n_rows ? row : n_rows - 1;
        nid[rp] = __ldg(c_cate_pad + (size_t)vrow * NGH + sub);
    }

    // ---- Phase 1: attention, 2 rows per iteration ----
#pragma unroll 1
    for (int rp = 0; rp < RPW / 2; rp++) {
        int row  = rowbase + 2 * rp + half;
        int vrow = row < n_rows ? row : n_rows - 1;
        int nidx = nid[rp];

        uint2 us = __ldg((const uint2*)g_rs_h + (size_t)vrow * 16 + sub);
        float2 sf0 = __half22float2(*reinterpret_cast<__half2*>(&us.x));
        float2 sf1 = __half22float2(*reinterpret_cast<__half2*>(&us.y));
        float2 ss = g_ss[vrow];                 // (scale, selfsim)

        float dtp[16];
#pragma unroll
        for (int j = 0; j < 16; j++) {
            int p = __shfl_sync(FULL, nidx, base + j);
            uint2 u = __ldg((const uint2*)g_rs_h + (size_t)p * 16 + sub);
            float2 f0 = __half22float2(*reinterpret_cast<__half2*>(&u.x));
            float2 f1 = __half22float2(*reinterpret_cast<__half2*>(&u.y));
            dtp[j] = fmaf(f0.x, sf0.x, fmaf(f0.y, sf0.y,
                      fmaf(f1.x, sf1.x, f1.y * sf1.y)));
        }

#pragma unroll
        for (int i = 0; i < 8; i++) dtp[i] = bmerge(dtp[i], dtp[i + 8], 8, lane);
#pragma unroll
        for (int i = 0; i < 4; i++) dtp[i] = bmerge(dtp[i], dtp[i + 4], 4, lane);
#pragma unroll
        for (int i = 0; i < 2; i++) dtp[i] = bmerge(dtp[i], dtp[i + 2], 2, lane);
        dtp[0] = bmerge(dtp[0], dtp[1], 1, lane);

        float miu = (nidx < v_cates - 1) ? __expf(dtp[0]) : 0.f;

        float dv = miu;
#pragma unroll
        for (int o = 8; o >= 1; o >>= 1)
            dv += __shfl_xor_sync(FULL, dv, o);

        float miu_self = (vrow < v_cates - 1) ? __expf(ss.y) : 0.f;
        float rden = 1.0f / (dv + miu_self + EPSF);

        // aggregation: self + 16 neighbors, packed FFMA2, float4 lanes
        ulonglong2 cs = __ldg((const ulonglong2*)(cate_emb + (size_t)vrow * D) + sub);
        ull msd = pk2(miu_self, miu_self);
        ull acc01, acc23;
        fma2(acc01, msd, cs.x, pk2(0.f, 0.f));
        fma2(acc23, msd, cs.y, pk2(0.f, 0.f));
#pragma unroll
        for (int j = 0; j < 16; j++) {
            float m = __shfl_sync(FULL, miu, base + j);
            int   p = __shfl_sync(FULL, nidx, base + j);
            ulonglong2 cv = __ldg((const ulonglong2*)(cate_emb + (size_t)p * D) + sub);
            ull mm = pk2(m, m);
            fma2(acc01, mm, cv.x, acc01);
            fma2(acc23, mm, cv.y, acc23);
        }
        float2 g01 = upk2(acc01);
        float2 g23 = upk2(acc23);

        // h store (fp16): rs part at e=4sub..4sub+3, agg at e=64+4sub..
        int rt = warp * RPW + 2 * rp + half;
        __half* hrow = sA + rt * ASTRIDE;
        float sc = ss.x;
        __half2 p0 = __floats2half2_rn(sf0.x * sc, sf0.y * sc);
        __half2 p1 = __floats2half2_rn(sf1.x * sc, sf1.y * sc);
        uint2 w0;
        w0.x = *reinterpret_cast<unsigned int*>(&p0);
        w0.y = *reinterpret_cast<unsigned int*>(&p1);
        *(uint2*)(hrow + 4 * sub) = w0;

        __half2 q0 = __floats2half2_rn(g01.x * rden, g01.y * rden);
        __half2 q1 = __floats2half2_rn(g23.x * rden, g23.y * rden);
        uint2 w1;
        w1.x = *reinterpret_cast<unsigned int*>(&q0);
        w1.y = *reinterpret_cast<unsigned int*>(&q1);
        *(uint2*)(hrow + 64 + 4 * sub) = w1;
    }
    __syncwarp();

    // ---- Phase 2: HMMA matvec, 16 rows x 64 cols per warp ----
    int gid  = lane >> 2;      // 0..7
    int tid4 = lane & 3;       // 0..3

    float acc[8][4];
#pragma unroll
    for (int n = 0; n < 8; n++)
#pragma unroll
        for (int i = 0; i < 4; i++) acc[n][i] = 0.f;

    const __half* a_base0 = sA + (warp * RPW + gid) * ASTRIDE + tid4 * 2;
    const __half* a_base1 = a_base0 + 8 * ASTRIDE;

#pragma unroll
    for (int k = 0; k < 8; k++) {
        uint32_t a0 = *(const uint32_t*)(a_base0 + k * 16);
        uint32_t a1 = *(const uint32_t*)(a_base1 + k * 16);
        uint32_t a2 = *(const uint32_t*)(a_base0 + k * 16 + 8);
        uint32_t a3 = *(const uint32_t*)(a_base1 + k * 16 + 8);
#pragma unroll
        for (int n = 0; n < 8; n++) {
            uint2 bf = __ldg(&g_Bfrag[(k * 8 + n) * 32 + lane]);
            mma16816(acc[n], a0, a1, a2, a3, bf.x, bf.y);
        }
    }

    // ---- epilogue: bias + ELU + direct stores ----
    int grow0 = rowbase + gid;
    int grow1 = grow0 + 8;
#pragma unroll
    for (int n = 0; n < 8; n++) {
        int col = n * 8 + tid4 * 2;
        float2 bb = *(const float2*)(agg_b + col);
        if (grow0 < n_rows) {
            float v0 = acc[n][0] + bb.x;
            float v1 = acc[n][1] + bb.y;
            v0 = v0 > 0.f ? v0 : expm1f(v0);
            v1 = v1 > 0.f ? v1 : expm1f(v1);
            *(float2*)(out + (size_t)grow0 * D + col) = make_float2(v0, v1);
        }
        if (grow1 < n_rows) {
            float v2 = acc[n][2] + bb.x;
            float v3 = acc[n][3] + bb.y;
            v2 = v2 > 0.f ? v2 : expm1f(v2);
            v3 = v3 > 0.f ? v3 : expm1f(v3);
            *(float2*)(out + (size_t)grow1 * D + col) = make_float2(v2, v3);
        }
    }
}

// ---------------------------------------------------------------------------
// Inputs (metadata order):
//  0 cids, 1 cate_emb_w [Vc,64], 2 scene_emb_w [Vs,64], 3 cate_scene_pad [N,10],
//  4 c_cate_pad [N,16], 5 agg_W [64,128], 6 agg_b [64]   -> out f32 [N,64]
// ---------------------------------------------------------------------------
extern "C" void kernel_launch(void* const* d_in, const int* in_sizes, int n_in,
                              void* d_out, int out_size) {
    const float* cate_emb       = (const float*)d_in[1];
    const float* scene_emb      = (const float*)d_in[2];
    const int*   cate_scene_pad = (const int*)d_in[3];
    const int*   c_cate_pad     = (const int*)d_in[4];
    const float* agg_W          = (const float*)d_in[5];
    const float* agg_b          = (const float*)d_in[6];
    float* out = (float*)d_out;

    int n_rows  = in_sizes[4] / NGH;   // 100000
    int v_cates = in_sizes[1] / D;     // 100000

    int threadsA = 256;
    int blocksA = (n_rows * 16 + threadsA - 1) / threadsA;
    rowsum_kernel<<<blocksA, threadsA>>>(scene_emb, cate_scene_pad, agg_W, n_rows);

    int blocksB = (n_rows + RPB - 1) / RPB;
    main_kernel<<<blocksB, 256>>>(cate_emb, c_cate_pad, agg_b,
                                  out, n_rows, v_cates);
}